// round 17
// baseline (speedup 1.0000x reference)
#include <cuda_runtime.h>

// ============================================================================
// EquivariantSpatialConv: fused 3x3 replicate-pad depthwise spatial average
// + fully-connected CG tensor product (irreps 1x4e + 1x6e) + residual.
//
// R17: output-layout staging. acc is written straight into output-ordered
// smem (s4[ty*288+tx*9+k], s6[ty*416+tx*13+k]; 9 and 13 coprime 32 ->
// conflict-free STS), so the store loop is a pure contiguous LDS.128 +
// STG.128 copy -- no LUTs, no scattered gathers (R16's L1 59% regression).
// Arithmetic bit-identical to R13/R14/R16.
// ============================================================================

#define DEVHOST __host__ __device__

// ---------------- compile-time scalar math ----------------
DEVHOST constexpr double cfact(int n) {
    double r = 1.0;
    for (int i = 2; i <= n; ++i) r *= (double)i;
    return r;
}

DEVHOST constexpr double csqrt(double x) {
    if (x <= 0.0) return 0.0;
    double g = x > 1.0 ? x : 1.0;
    for (int it = 0; it < 48; ++it) g = 0.5 * (g + x / g);
    return g;
}

struct CD { double re, im; };
DEVHOST constexpr CD cmul(CD a, CD b) {
    return CD{a.re * b.re - a.im * b.im, a.re * b.im + a.im * b.re};
}
DEVHOST constexpr CD cconj(CD a) { return CD{a.re, -a.im}; }

DEVHOST constexpr double su2_cg(int j1, int j2, int j3, int m1, int m2, int m3) {
    if (m3 != m1 + m2) return 0.0;
    if (m1 < -j1 || m1 > j1 || m2 < -j2 || m2 > j2 || m3 < -j3 || m3 > j3) return 0.0;
    double pref0 = (2.0 * j3 + 1.0) * cfact(j1 + j2 - j3) * cfact(j1 - j2 + j3) *
                   cfact(-j1 + j2 + j3) / cfact(j1 + j2 + j3 + 1);
    double pref = csqrt(pref0 * cfact(j3 + m3) * cfact(j3 - m3) * cfact(j1 - m1) *
                        cfact(j1 + m1) * cfact(j2 - m2) * cfact(j2 + m2));
    int kmin = 0;
    if (-(j3 - j2 + m1) > kmin) kmin = -(j3 - j2 + m1);
    if (-(j3 - j1 - m2) > kmin) kmin = -(j3 - j1 - m2);
    int kmax = j1 + j2 - j3;
    if (j1 - m1 < kmax) kmax = j1 - m1;
    if (j2 + m2 < kmax) kmax = j2 + m2;
    double s = 0.0;
    for (int k = kmin; k <= kmax; ++k) {
        double d = cfact(k) * cfact(j1 + j2 - j3 - k) * cfact(j1 - m1 - k) *
                   cfact(j2 + m2 - k) * cfact(j3 - j2 + m1 + k) * cfact(j3 - j1 - m2 + k);
        s += ((k & 1) ? -1.0 : 1.0) / d;
    }
    return pref * s;
}

DEVHOST constexpr CD qent(int l, int r, int c) {
    constexpr double S2 = 0.70710678118654752440;
    int m = r - l;
    CD v{0.0, 0.0};
    if (m < 0) {
        if (c == l - m)      v = CD{S2, 0.0};
        else if (c == l + m) v = CD{0.0, -S2};
    } else if (m == 0) {
        if (c == l) v = CD{1.0, 0.0};
    } else {
        double sg = (m & 1) ? -1.0 : 1.0;
        if (c == l + m)      v = CD{sg * S2, 0.0};
        else if (c == l - m) v = CD{0.0, sg * S2};
    }
    int ph = l & 3;
    CD f = (ph == 0) ? CD{1, 0} : (ph == 1) ? CD{0, -1} : (ph == 2) ? CD{-1, 0} : CD{0, 1};
    return cmul(v, f);
}

DEVHOST constexpr double real_cg_entry(int l1, int l2, int l3, int a, int b, int c) {
    int d1 = a >= l1 ? a - l1 : l1 - a;
    int d2 = b >= l2 ? b - l2 : l2 - b;
    int d3 = c >= l3 ? c - l3 : l3 - c;
    CD sum{0.0, 0.0};
    int ni = d1 ? 2 : 1;
    int nk = d2 ? 2 : 1;
    for (int si = 0; si < ni; ++si) {
        int i = d1 ? (si ? l1 + d1 : l1 - d1) : l1;
        int m1 = i - l1;
        CD q1 = qent(l1, i, a);
        for (int sk = 0; sk < nk; ++sk) {
            int k = d2 ? (sk ? l2 + d2 : l2 - d2) : l2;
            int m2 = k - l2;
            int m3 = m1 + m2;
            if (m3 < -l3 || m3 > l3) continue;
            int am3 = m3 < 0 ? -m3 : m3;
            if (am3 != d3) continue;
            int n = l3 + m3;
            CD q2 = qent(l2, k, b);
            CD q3 = cconj(qent(l3, c, n));
            double C = su2_cg(l1, l2, l3, m1, m2, m3);
            CD t = cmul(cmul(q1, q2), q3);
            sum.re += t.re * C;
            sum.im += t.im * C;
        }
    }
    return sum.re;
}

template <int L1, int L2, int L3>
struct CGT {
    float v[2 * L1 + 1][2 * L2 + 1][2 * L3 + 1];
};

template <int L1, int L2, int L3>
DEVHOST constexpr CGT<L1, L2, L3> make_cg() {
    double tmp[2 * L1 + 1][2 * L2 + 1][2 * L3 + 1] = {};
    double ss = 0.0;
    for (int a = 0; a < 2 * L1 + 1; ++a)
        for (int b = 0; b < 2 * L2 + 1; ++b)
            for (int c = 0; c < 2 * L3 + 1; ++c) {
                double e = real_cg_entry(L1, L2, L3, a, b, c);
                tmp[a][b][c] = e;
                ss += e * e;
            }
    double inv = 1.0 / csqrt(ss);
    CGT<L1, L2, L3> r{};
    for (int a = 0; a < 2 * L1 + 1; ++a)
        for (int b = 0; b < 2 * L2 + 1; ++b)
            for (int c = 0; c < 2 * L3 + 1; ++c)
                r.v[a][b][c] = (float)(tmp[a][b][c] * inv);
    return r;
}

// Namespace-scope constexpr CG tensors (static storage: usable in constant
// expressions from any lambda depth inside function templates).
template <int L1, int L2, int L3>
inline constexpr CGT<L1, L2, L3> CG = make_cg<L1, L2, L3>();

// ---------------- compile-time unrolling helpers ----------------
template <int V> struct IC { static constexpr int value = V; };

template <int N, int I = 0, class F>
__device__ __forceinline__ void sfor(F&& f) {
    if constexpr (I < N) {
        f(IC<I>{});
        sfor<N, I + 1>(static_cast<F&&>(f));
    }
}

template <class T>
DEVHOST constexpr bool rowany(const T& t, int a, int b, int dk) {
    for (int k = 0; k < dk; ++k)
        if (t.v[a][b][k] != 0.0f) return true;
    return false;
}
template <class T>
DEVHOST constexpr bool rowany2(const T& t, int a, int b, int dk) {
    for (int k = 0; k < dk; ++k)
        if (t.v[a][b][k] != 0.0f || t.v[b][a][k] != 0.0f) return true;
    return false;
}
template <class T>
DEVHOST constexpr bool symk(const T& t, int a, int b, int dk) {
    for (int k = 0; k < dk; ++k)
        if (t.v[a][b][k] != t.v[b][a][k]) return false;
    return true;
}
template <class TA, class TB>
DEVHOST constexpr bool eqk(const TA& A, int i, int j, const TB& B, int bi, int bj, int dk) {
    for (int k = 0; k < dk; ++k)
        if (A.v[i][j][k] != B.v[bi][bj][k]) return false;
    return true;
}

// ---------------- packed f32x2 helpers ----------------
__device__ __forceinline__ float2 f2fma(float2 a, float2 b, float2 c) {
    float2 d;
    asm("fma.rn.f32x2 %0, %1, %2, %3;"
        : "=l"(*reinterpret_cast<unsigned long long*>(&d))
        : "l"(*reinterpret_cast<unsigned long long*>(&a)),
          "l"(*reinterpret_cast<unsigned long long*>(&b)),
          "l"(*reinterpret_cast<unsigned long long*>(&c)));
    return d;
}
__device__ __forceinline__ float2 f2mul(float2 a, float2 b) {
    float2 d;
    asm("mul.rn.f32x2 %0, %1, %2;"
        : "=l"(*reinterpret_cast<unsigned long long*>(&d))
        : "l"(*reinterpret_cast<unsigned long long*>(&a)),
          "l"(*reinterpret_cast<unsigned long long*>(&b)));
    return d;
}

// ---------------- tensor-product blocks ----------------
// Diagonal block (L,L,*): UNWEIGHTED accumulation into z[22]
// (z[0..8] <- CG<L,L,4>, z[9..21] <- CG<L,L,6>); weights applied by caller.
template <int L, int O>
__device__ __forceinline__ void tp_diag_z(const float* __restrict__ x1,
                                          const float* __restrict__ x2,
                                          float* __restrict__ z) {
    constexpr int D = 2 * L + 1;
    sfor<D>([&](auto I) {
        constexpr int i = decltype(I)::value;
        sfor<D>([&](auto J) {
            constexpr int j = decltype(J)::value;
            if constexpr (j >= i) {
                constexpr bool l0 = rowany2(CG<L, L, 4>, i, j, 9);
                constexpr bool l1 = rowany2(CG<L, L, 6>, i, j, 13);
                if constexpr (l0 || l1) {
                    if constexpr (i == j) {
                        float p = x1[O + i] * x2[O + i];
                        sfor<9>([&](auto K) {
                            constexpr int k = decltype(K)::value;
                            constexpr float cv = CG<L, L, 4>.v[i][i][k];
                            if constexpr (cv != 0.0f) z[k] = __fmaf_rn(cv, p, z[k]);
                        });
                        sfor<13>([&](auto K) {
                            constexpr int k = decltype(K)::value;
                            constexpr float cv = CG<L, L, 6>.v[i][i][k];
                            if constexpr (cv != 0.0f) z[9 + k] = __fmaf_rn(cv, p, z[9 + k]);
                        });
                    } else if constexpr (symk(CG<L, L, 4>, i, j, 9) && symk(CG<L, L, 6>, i, j, 13)) {
                        float s = __fmaf_rn(x1[O + j], x2[O + i], x1[O + i] * x2[O + j]);
                        sfor<9>([&](auto K) {
                            constexpr int k = decltype(K)::value;
                            constexpr float cv = CG<L, L, 4>.v[i][j][k];
                            if constexpr (cv != 0.0f) z[k] = __fmaf_rn(cv, s, z[k]);
                        });
                        sfor<13>([&](auto K) {
                            constexpr int k = decltype(K)::value;
                            constexpr float cv = CG<L, L, 6>.v[i][j][k];
                            if constexpr (cv != 0.0f) z[9 + k] = __fmaf_rn(cv, s, z[9 + k]);
                        });
                    } else {
                        // fallback (not expected for even l1+l2+l3): both orders
                        float p1 = x1[O + i] * x2[O + j];
                        float p2 = x1[O + j] * x2[O + i];
                        sfor<9>([&](auto K) {
                            constexpr int k = decltype(K)::value;
                            constexpr float c1 = CG<L, L, 4>.v[i][j][k];
                            constexpr float c2 = CG<L, L, 4>.v[j][i][k];
                            if constexpr (c1 != 0.0f) z[k] = __fmaf_rn(c1, p1, z[k]);
                            if constexpr (c2 != 0.0f) z[k] = __fmaf_rn(c2, p2, z[k]);
                        });
                        sfor<13>([&](auto K) {
                            constexpr int k = decltype(K)::value;
                            constexpr float c1 = CG<L, L, 6>.v[i][j][k];
                            constexpr float c2 = CG<L, L, 6>.v[j][i][k];
                            if constexpr (c1 != 0.0f) z[9 + k] = __fmaf_rn(c1, p1, z[9 + k]);
                            if constexpr (c2 != 0.0f) z[9 + k] = __fmaf_rn(c2, p2, z[9 + k]);
                        });
                    }
                }
            }
        });
    });
}

// Cross block with j-outer prescaling: for each j, A=w*x2[9+j] / B=w*x1[9+j]
// fold the path weights into per-j scalars; each (i,j) pair then costs
// u = fma(x2[i], B, x1[i]*A) per live output (2 ops instead of 3).
__device__ __forceinline__ void tp_cross(const float* __restrict__ x1,
                                         const float* __restrict__ x2,
                                         float* __restrict__ acc,
                                         float wA0, float wA1, float wB0, float wB1) {
    sfor<13>([&](auto J) {
        constexpr int j = decltype(J)::value;
        // per-j prescaled operands (transient registers)
        float A0 = wA0 * x2[9 + j];   // (4,6,4): x1[i] * A0
        float B0 = wB0 * x1[9 + j];   // (6,4,4): x2[i] * B0
        float A1 = wA1 * x2[9 + j];   // (4,6,6)
        float B1 = wB1 * x1[9 + j];   // (6,4,6)
        sfor<9>([&](auto I) {
            constexpr int i = decltype(I)::value;
            constexpr bool a0 = rowany(CG<4, 6, 4>, i, j, 9);
            constexpr bool b0 = rowany(CG<6, 4, 4>, j, i, 9);
            constexpr bool a1 = rowany(CG<4, 6, 6>, i, j, 13);
            constexpr bool b1 = rowany(CG<6, 4, 6>, j, i, 13);
            if constexpr (a0 || b0) {
                if constexpr (a0 && b0 && eqk(CG<4, 6, 4>, i, j, CG<6, 4, 4>, j, i, 9)) {
                    float u = __fmaf_rn(x2[i], B0, x1[i] * A0);
                    sfor<9>([&](auto K) {
                        constexpr int k = decltype(K)::value;
                        constexpr float cv = CG<4, 6, 4>.v[i][j][k];
                        if constexpr (cv != 0.0f) acc[k] = __fmaf_rn(cv, u, acc[k]);
                    });
                } else {
                    if constexpr (a0) {
                        float t1 = x1[i] * A0;
                        sfor<9>([&](auto K) {
                            constexpr int k = decltype(K)::value;
                            constexpr float cv = CG<4, 6, 4>.v[i][j][k];
                            if constexpr (cv != 0.0f) acc[k] = __fmaf_rn(cv, t1, acc[k]);
                        });
                    }
                    if constexpr (b0) {
                        float t2 = x2[i] * B0;
                        sfor<9>([&](auto K) {
                            constexpr int k = decltype(K)::value;
                            constexpr float cv = CG<6, 4, 4>.v[j][i][k];
                            if constexpr (cv != 0.0f) acc[k] = __fmaf_rn(cv, t2, acc[k]);
                        });
                    }
                }
            }
            if constexpr (a1 || b1) {
                if constexpr (a1 && b1 && eqk(CG<4, 6, 6>, i, j, CG<6, 4, 6>, j, i, 13)) {
                    float u = __fmaf_rn(x2[i], B1, x1[i] * A1);
                    sfor<13>([&](auto K) {
                        constexpr int k = decltype(K)::value;
                        constexpr float cv = CG<4, 6, 6>.v[i][j][k];
                        if constexpr (cv != 0.0f) acc[9 + k] = __fmaf_rn(cv, u, acc[9 + k]);
                    });
                } else {
                    if constexpr (a1) {
                        float t1 = x1[i] * A1;
                        sfor<13>([&](auto K) {
                            constexpr int k = decltype(K)::value;
                            constexpr float cv = CG<4, 6, 6>.v[i][j][k];
                            if constexpr (cv != 0.0f) acc[9 + k] = __fmaf_rn(cv, t1, acc[9 + k]);
                        });
                    }
                    if constexpr (b1) {
                        float t2 = x2[i] * B1;
                        sfor<13>([&](auto K) {
                            constexpr int k = decltype(K)::value;
                            constexpr float cv = CG<6, 4, 6>.v[j][i][k];
                            if constexpr (cv != 0.0f) acc[9 + k] = __fmaf_rn(cv, t2, acc[9 + k]);
                        });
                    }
                }
            }
        });
    });
}

// ---------------- kernel ----------------
constexpr int H = 768, W = 768;
constexpr int TX = 32, TY = 4;             // 128-thread tile
constexpr int NT = TX * TY;                // 128
constexpr int HTX = TX + 2, HTY = TY + 2;  // 34 x 6 haloed tile
constexpr int NPIX = HTX * HTY;            // 204
constexpr int R4 = TX * 9;                 // 288 floats per out4 row
constexpr int R6 = TX * 13;                // 416 floats per out6 row

__global__ void __launch_bounds__(NT, 7) eq_spatial_tp_kernel(
    const float* __restrict__ f4, const float* __restrict__ f6,
    const float* __restrict__ sw, const float* __restrict__ wp,
    float* __restrict__ out4, float* __restrict__ out6) {
    // float4-group, pixel-major smem: groups 0-4 hold ch 4g..4g+3, group 5 ch 20-21.
    // After the TP this memory is dead and is re-used as the OUTPUT-LAYOUT
    // staging buffer: s4 = 4x288 floats, s6 = 4x416 floats (11264 B < 17952 B).
    __shared__ float4 tile4[5][NPIX];   // 16320 B
    __shared__ float2 tile5[NPIX];      // 1632 B -> 17952 B, 7 CTAs = 126 KB

    const int tid = threadIdx.x;
    const int bx = blockIdx.x, by = blockIdx.y;
    const int gx0 = bx * TX - 1, gy0 = by * TY - 1;

    // hoist weight loads so their latency overlaps the tile load
    float2 swp[9];
#pragma unroll
    for (int q = 0; q < 9; ++q) {
        float s = sw[q];
        swp[q] = make_float2(s, s);
    }
    float wcomb[8];
#pragma unroll
    for (int p = 0; p < 8; ++p) wcomb[p] = 0.5f * wp[p];  // ALPHA = 1/sqrt(4)

    // ---- pixel-outer haloed-tile load (2 pixels/thread, compile-time offsets) ----
#pragma unroll
    for (int pix = tid; pix < NPIX; pix += NT) {
        int r = pix / HTX, c = pix - r * HTX;
        int gy = gy0 + r; gy = gy < 0 ? 0 : (gy > H - 1 ? H - 1 : gy);
        int gx = gx0 + c; gx = gx < 0 ? 0 : (gx > W - 1 ? W - 1 : gx);
        int g = gy * W + gx;
        const float* p4 = f4 + g * 9;
        const float* p6 = f6 + g * 13;
        float v[22];
#pragma unroll
        for (int ch = 0; ch < 9; ++ch) v[ch] = p4[ch];
#pragma unroll
        for (int ch = 0; ch < 13; ++ch) v[9 + ch] = p6[ch];
#pragma unroll
        for (int gg = 0; gg < 5; ++gg)
            tile4[gg][pix] = make_float4(v[4 * gg], v[4 * gg + 1], v[4 * gg + 2], v[4 * gg + 3]);
        tile5[pix] = make_float2(v[20], v[21]);
    }
    __syncthreads();

    const int tx = tid & 31, ty = tid >> 5;

    // x1 = center features; x2 = weighted 3x3 neighbor average (packed f32x2)
    __align__(16) float x1[22];
    __align__(8) float x2[22];
    float2* x1v = reinterpret_cast<float2*>(x1);
    float2* x2v = reinterpret_cast<float2*>(x2);
    {
        const int cpix = (ty + 1) * HTX + (tx + 1);
#pragma unroll
        for (int gg = 0; gg < 5; ++gg) {
            float4 t = tile4[gg][cpix];
            x1v[2 * gg] = make_float2(t.x, t.y);
            x1v[2 * gg + 1] = make_float2(t.z, t.w);
        }
        x1v[10] = tile5[cpix];
#pragma unroll
        for (int p = 0; p < 11; ++p) x2v[p] = f2mul(swp[4], x1v[p]);
    }
#pragma unroll
    for (int dy = 0; dy < 3; ++dy)
#pragma unroll
        for (int dx = 0; dx < 3; ++dx) {
            if (dy == 1 && dx == 1) continue;
            const int npix = (ty + dy) * HTX + (tx + dx);
            const float2 wq = swp[dy * 3 + dx];
#pragma unroll
            for (int gg = 0; gg < 5; ++gg) {
                float4 t = tile4[gg][npix];
                x2v[2 * gg] = f2fma(wq, make_float2(t.x, t.y), x2v[2 * gg]);
                x2v[2 * gg + 1] = f2fma(wq, make_float2(t.z, t.w), x2v[2 * gg + 1]);
            }
            x2v[10] = f2fma(wq, tile5[npix], x2v[10]);
        }

    // ---- TP, ordered for register liveness ----
    float acc[22];
    {
        // diag44 unweighted -> z; acc born as x1 + w*z (z dies into acc)
        float z[22];
#pragma unroll
        for (int k = 0; k < 22; ++k) z[k] = 0.0f;
        tp_diag_z<4, 0>(x1, x2, z);
#pragma unroll
        for (int k = 0; k < 9; ++k) acc[k] = __fmaf_rn(wcomb[0], z[k], x1[k]);
#pragma unroll
        for (int k = 0; k < 13; ++k) acc[9 + k] = __fmaf_rn(wcomb[1], z[9 + k], x1[9 + k]);
    }

    // cross block (merged + j-prescaled), weighted into acc
    tp_cross(x1, x2, acc, wcomb[2], wcomb[3], wcomb[4], wcomb[5]);

    {
        // diag66 unweighted -> z (x1[0..8]/x2[0..8] dead by now)
        float z[22];
#pragma unroll
        for (int k = 0; k < 22; ++k) z[k] = 0.0f;
        tp_diag_z<6, 9>(x1, x2, z);
#pragma unroll
        for (int k = 0; k < 9; ++k) acc[k] = __fmaf_rn(wcomb[6], z[k], acc[k]);
#pragma unroll
        for (int k = 0; k < 13; ++k) acc[9 + k] = __fmaf_rn(wcomb[7], z[9 + k], acc[9 + k]);
    }

    // ---- output-layout staging + contiguous float4 copy-out ----
    __syncthreads();   // all tile reads done; smem becomes the staging buffer
    float* resf = reinterpret_cast<float*>(tile4);
    float* s4 = resf;                 // [TY][R4] = 4 x 288 floats
    float* s6 = resf + TY * R4;       // [TY][R6] = 4 x 416 floats
    {
        // tx*9 / tx*13: 9,13 coprime 32 -> conflict-free STS per k
        const int b4 = ty * R4 + tx * 9;
#pragma unroll
        for (int k = 0; k < 9; ++k) s4[b4 + k] = acc[k];
        const int b6 = ty * R6 + tx * 13;
#pragma unroll
        for (int k = 0; k < 13; ++k) s6[b6 + k] = acc[9 + k];
    }
    __syncthreads();

    // contiguous, aligned copies: per row 72 (out4) + 104 (out6) float4s
    const int obase4 = (by * TY * W + bx * TX) * 9;
    const int obase6 = (by * TY * W + bx * TX) * 13;
#pragma unroll
    for (int row = 0; row < TY; ++row) {
        const float4* src4 = reinterpret_cast<const float4*>(s4 + row * R4);
        const float4* src6 = reinterpret_cast<const float4*>(s6 + row * R6);
        float4* o4 = reinterpret_cast<float4*>(out4 + obase4 + row * (W * 9));
        float4* o6 = reinterpret_cast<float4*>(out6 + obase6 + row * (W * 13));
        for (int u = tid; u < 72 + 104; u += NT) {
            if (u < 72) o4[u] = src4[u];
            else o6[u - 72] = src6[u - 72];
        }
    }
}

extern "C" void kernel_launch(void* const* d_in, const int* in_sizes, int n_in,
                              void* d_out, int out_size) {
    const float* f4 = (const float*)d_in[0];
    const float* f6 = (const float*)d_in[1];
    const float* sw = (const float*)d_in[2];  // spatial_weights [3,3]
    const float* wp = (const float*)d_in[3];  // w_paths [8]
    float* out = (float*)d_out;
    const size_t N = (size_t)H * W;

    dim3 grid(W / TX, H / TY);  // 24 x 192
    eq_spatial_tp_kernel<<<grid, NT>>>(f4, f6, sw, wp, out, out + N * 9);
}